// round 4
// baseline (speedup 1.0000x reference)
#include <cuda_runtime.h>

// SPU transformer bound propagation — pure elementwise, HBM-bound.
// Traffic floor: 320 MiB. R3 (32 regs, occ 83%, ldcs/stcs): 6710 GB/s, 45.6us.
// R4: single-wave persistent grid-stride (1184 CTAs = 148 SMs x 8) to remove
// ~13 wave transitions. Loop body identical, no front-batching (regs stay low).

__device__ __forceinline__ float spu_f(float x) {
    // x>=0: x*x - 0.5 ; x<0: sigmoid(-x) - 1 = -e^x / (1 + e^x)
    float ex = __expf(x);
    float negv = -ex / (1.0f + ex);
    float posv = fmaf(x, x, -0.5f);
    return x >= 0.0f ? posv : negv;
}

__device__ __forceinline__ void spu_elem(
    float l, float u,
    float p1l, float p1u,
    float q1l, float q1u,
    float b0l, float b0u,
    float& out_lo, float& out_hi)
{
    float sl = spu_f(l);
    float su = spu_f(u);

    bool neg   = (u <= 0.0f);
    bool pos   = (l >= 0.0f);
    bool cross = !(neg || pos);

    float slope = (su - sl) / (u - l);   // u-l >= 0.02, safe

    float s0 = neg ? slope : 0.0f;
    float s1 = neg ? 0.0f  : slope;     // pos|cross == !neg

    bool neg_slope = (slope < 0.0f);
    float lo = neg_slope ? su : sl;
    float hi = neg_slope ? sl : su;
    lo = cross ? -0.5f : lo;

    float sh1 = fmaf(-s1, u, su);
    float sh0 = fmaf(-s0, l, sl);
    sh0 = cross ? -0.5f : sh0;
    sh1 = neg   ? sl    : sh1;

    float s1p = fmaxf(s1, 0.0f), s1n = fminf(s1, 0.0f);
    float s0p = fmaxf(s0, 0.0f), s0n = fminf(s0, 0.0f);

    float UBM = fmaf(s1p, p1u, s1n * p1l);
    float UBV = fmaf(s1p, q1u, fmaf(s1n, q1l, sh1));
    float LBM = fmaf(s0p, p1l, s0n * p1u);
    float LBV = fmaf(s0n, q1l, fmaf(s0p, q1u, sh0));

    float lower = fmaf(fmaxf(LBM, 0.0f), b0l, fmaf(fminf(LBM, 0.0f), b0u, LBV));
    float upper = fmaf(fmaxf(UBM, 0.0f), b0u, fmaf(fminf(UBM, 0.0f), b0l, UBV));

    out_lo = (lower > lo) ? lower : lo;
    out_hi = (upper < hi) ? upper : hi;
}

__global__ void __launch_bounds__(256)
spu_kernel(const float4* __restrict__ bounds,
           const float4* __restrict__ slopes_prev,
           const float4* __restrict__ shifts_prev,
           const float4* __restrict__ bounds_prev,
           float4* __restrict__ out,
           int n_vec)   // n_vec = N/2 float4s
{
    int stride = gridDim.x * blockDim.x;

    // Grid-stride, single wave. Each iteration: 4 independent LDG.128,
    // compute, STG.128. Next iteration's loads have no dependence on the
    // store, so MLP across iterations is preserved by the scoreboard.
#pragma unroll 2
    for (int i = blockIdx.x * blockDim.x + threadIdx.x; i < n_vec; i += stride) {
        float4 b  = __ldcs(&bounds[i]);
        float4 sp = __ldcs(&slopes_prev[i]);
        float4 sh = __ldcs(&shifts_prev[i]);
        float4 bp = __ldcs(&bounds_prev[i]);

        float4 r;
        spu_elem(b.x, b.y, sp.x, sp.y, sh.x, sh.y, bp.x, bp.y, r.x, r.y);
        spu_elem(b.z, b.w, sp.z, sp.w, sh.z, sh.w, bp.z, bp.w, r.z, r.w);

        __stcs(&out[i], r);
    }
}

extern "C" void kernel_launch(void* const* d_in, const int* in_sizes, int n_in,
                              void* d_out, int out_size) {
    // metadata order: bounds (N,2), slopes_prev (N,2), shifts_prev (N,2), bounds_prev (N,2)
    const float4* bounds      = (const float4*)d_in[0];
    const float4* slopes_prev = (const float4*)d_in[1];
    const float4* shifts_prev = (const float4*)d_in[2];
    const float4* bounds_prev = (const float4*)d_in[3];
    float4* out = (float4*)d_out;

    int n_floats = in_sizes[0];          // N*2
    int n_vec = n_floats / 4;            // float4 count

    // One wave: 148 SMs x 8 CTAs (32-40 regs, 256 thr -> 8 CTA/SM limit).
    int threads = 256;
    int blocks = 148 * 8;
    int max_blocks = (n_vec + threads - 1) / threads;
    if (blocks > max_blocks) blocks = max_blocks;
    spu_kernel<<<blocks, threads>>>(bounds, slopes_prev, shifts_prev, bounds_prev, out, n_vec);
}

// round 5
// speedup vs baseline: 1.0780x; 1.0780x over previous
#include <cuda_runtime.h>

// SPU transformer bound propagation — pure elementwise, HBM-bound.
// Traffic floor: 320 MiB (4 in + 1 out, fp32).
// R3 best: flat launch, 32 regs, occ 83%, ldcs/stcs -> 6710 GB/s, 45.6us kernel.
// R2 (unroll x4) and R4 (persistent grid-stride) both regressed via register
// pressure / occupancy loss. R5 = R3 body, 128-thread blocks (finer tail).

__device__ __forceinline__ float spu_f(float x) {
    // x>=0: x*x - 0.5 ; x<0: sigmoid(-x) - 1 = -e^x / (1 + e^x)
    float ex = __expf(x);
    float negv = -ex / (1.0f + ex);
    float posv = fmaf(x, x, -0.5f);
    return x >= 0.0f ? posv : negv;
}

__device__ __forceinline__ void spu_elem(
    float l, float u,
    float p1l, float p1u,
    float q1l, float q1u,
    float b0l, float b0u,
    float& out_lo, float& out_hi)
{
    float sl = spu_f(l);
    float su = spu_f(u);

    bool neg   = (u <= 0.0f);
    bool pos   = (l >= 0.0f);
    bool cross = !(neg || pos);

    float slope = (su - sl) / (u - l);   // u-l >= 0.02, safe

    float s0 = neg ? slope : 0.0f;
    float s1 = neg ? 0.0f  : slope;     // pos|cross == !neg

    bool neg_slope = (slope < 0.0f);
    float lo = neg_slope ? su : sl;
    float hi = neg_slope ? sl : su;
    lo = cross ? -0.5f : lo;

    float sh1 = fmaf(-s1, u, su);
    float sh0 = fmaf(-s0, l, sl);
    sh0 = cross ? -0.5f : sh0;
    sh1 = neg   ? sl    : sh1;

    float s1p = fmaxf(s1, 0.0f), s1n = fminf(s1, 0.0f);
    float s0p = fmaxf(s0, 0.0f), s0n = fminf(s0, 0.0f);

    float UBM = fmaf(s1p, p1u, s1n * p1l);
    float UBV = fmaf(s1p, q1u, fmaf(s1n, q1l, sh1));
    float LBM = fmaf(s0p, p1l, s0n * p1u);
    float LBV = fmaf(s0n, q1l, fmaf(s0p, q1u, sh0));

    float lower = fmaf(fmaxf(LBM, 0.0f), b0l, fmaf(fminf(LBM, 0.0f), b0u, LBV));
    float upper = fmaf(fmaxf(UBM, 0.0f), b0u, fmaf(fminf(UBM, 0.0f), b0l, UBV));

    out_lo = (lower > lo) ? lower : lo;
    out_hi = (upper < hi) ? upper : hi;
}

__global__ void __launch_bounds__(128)
spu_kernel(const float4* __restrict__ bounds,
           const float4* __restrict__ slopes_prev,
           const float4* __restrict__ shifts_prev,
           const float4* __restrict__ bounds_prev,
           float4* __restrict__ out,
           int n_vec)   // n_vec = N/2 float4s, each covering 2 elements
{
    int i = blockIdx.x * blockDim.x + threadIdx.x;
    if (i >= n_vec) return;

    float4 b  = __ldcs(&bounds[i]);
    float4 sp = __ldcs(&slopes_prev[i]);
    float4 sh = __ldcs(&shifts_prev[i]);
    float4 bp = __ldcs(&bounds_prev[i]);

    float4 r;
    spu_elem(b.x, b.y, sp.x, sp.y, sh.x, sh.y, bp.x, bp.y, r.x, r.y);
    spu_elem(b.z, b.w, sp.z, sp.w, sh.z, sh.w, bp.z, bp.w, r.z, r.w);

    __stcs(&out[i], r);
}

extern "C" void kernel_launch(void* const* d_in, const int* in_sizes, int n_in,
                              void* d_out, int out_size) {
    // metadata order: bounds (N,2), slopes_prev (N,2), shifts_prev (N,2), bounds_prev (N,2)
    const float4* bounds      = (const float4*)d_in[0];
    const float4* slopes_prev = (const float4*)d_in[1];
    const float4* shifts_prev = (const float4*)d_in[2];
    const float4* bounds_prev = (const float4*)d_in[3];
    float4* out = (float4*)d_out;

    int n_floats = in_sizes[0];          // N*2
    int n_vec = n_floats / 4;            // float4 count (N*2 divisible by 4)

    int threads = 128;
    int blocks = (n_vec + threads - 1) / threads;
    spu_kernel<<<blocks, threads>>>(bounds, slopes_prev, shifts_prev, bounds_prev, out, n_vec);
}

// round 6
// speedup vs baseline: 1.0793x; 1.0012x over previous
#include <cuda_runtime.h>

// SPU transformer bound propagation — pure elementwise, HBM-bound.
// Traffic floor: 320 MiB (4 in + 1 out, fp32). Achieved: ~6.7 TB/s (84% spec).
// Proven optimum structure (R3/R5): flat launch, 1 float4/array/thread,
// ldcs/stcs, 32 regs, max occupancy. R2 (unroll) & R4 (persistent) regressed
// via register pressure. R6: 512-thread blocks -> 64-warp/SM occupancy cap,
// 8192 CTAs. Zero register-count risk.

__device__ __forceinline__ float spu_f(float x) {
    // x>=0: x*x - 0.5 ; x<0: sigmoid(-x) - 1 = -e^x / (1 + e^x)
    float ex = __expf(x);
    float negv = -ex / (1.0f + ex);
    float posv = fmaf(x, x, -0.5f);
    return x >= 0.0f ? posv : negv;
}

__device__ __forceinline__ void spu_elem(
    float l, float u,
    float p1l, float p1u,
    float q1l, float q1u,
    float b0l, float b0u,
    float& out_lo, float& out_hi)
{
    float sl = spu_f(l);
    float su = spu_f(u);

    bool neg   = (u <= 0.0f);
    bool pos   = (l >= 0.0f);
    bool cross = !(neg || pos);

    float slope = (su - sl) / (u - l);   // u-l >= 0.02, safe

    float s0 = neg ? slope : 0.0f;
    float s1 = neg ? 0.0f  : slope;     // pos|cross == !neg

    bool neg_slope = (slope < 0.0f);
    float lo = neg_slope ? su : sl;
    float hi = neg_slope ? sl : su;
    lo = cross ? -0.5f : lo;

    float sh1 = fmaf(-s1, u, su);
    float sh0 = fmaf(-s0, l, sl);
    sh0 = cross ? -0.5f : sh0;
    sh1 = neg   ? sl    : sh1;

    float s1p = fmaxf(s1, 0.0f), s1n = fminf(s1, 0.0f);
    float s0p = fmaxf(s0, 0.0f), s0n = fminf(s0, 0.0f);

    float UBM = fmaf(s1p, p1u, s1n * p1l);
    float UBV = fmaf(s1p, q1u, fmaf(s1n, q1l, sh1));
    float LBM = fmaf(s0p, p1l, s0n * p1u);
    float LBV = fmaf(s0n, q1l, fmaf(s0p, q1u, sh0));

    float lower = fmaf(fmaxf(LBM, 0.0f), b0l, fmaf(fminf(LBM, 0.0f), b0u, LBV));
    float upper = fmaf(fmaxf(UBM, 0.0f), b0u, fmaf(fminf(UBM, 0.0f), b0l, UBV));

    out_lo = (lower > lo) ? lower : lo;
    out_hi = (upper < hi) ? upper : hi;
}

__global__ void __launch_bounds__(512)
spu_kernel(const float4* __restrict__ bounds,
           const float4* __restrict__ slopes_prev,
           const float4* __restrict__ shifts_prev,
           const float4* __restrict__ bounds_prev,
           float4* __restrict__ out,
           int n_vec)   // n_vec = N/2 float4s, each covering 2 elements
{
    int i = blockIdx.x * blockDim.x + threadIdx.x;
    if (i >= n_vec) return;

    float4 b  = __ldcs(&bounds[i]);
    float4 sp = __ldcs(&slopes_prev[i]);
    float4 sh = __ldcs(&shifts_prev[i]);
    float4 bp = __ldcs(&bounds_prev[i]);

    float4 r;
    spu_elem(b.x, b.y, sp.x, sp.y, sh.x, sh.y, bp.x, bp.y, r.x, r.y);
    spu_elem(b.z, b.w, sp.z, sp.w, sh.z, sh.w, bp.z, bp.w, r.z, r.w);

    __stcs(&out[i], r);
}

extern "C" void kernel_launch(void* const* d_in, const int* in_sizes, int n_in,
                              void* d_out, int out_size) {
    // metadata order: bounds (N,2), slopes_prev (N,2), shifts_prev (N,2), bounds_prev (N,2)
    const float4* bounds      = (const float4*)d_in[0];
    const float4* slopes_prev = (const float4*)d_in[1];
    const float4* shifts_prev = (const float4*)d_in[2];
    const float4* bounds_prev = (const float4*)d_in[3];
    float4* out = (float4*)d_out;

    int n_floats = in_sizes[0];          // N*2
    int n_vec = n_floats / 4;            // float4 count (N*2 divisible by 4)

    int threads = 512;
    int blocks = (n_vec + threads - 1) / threads;
    spu_kernel<<<blocks, threads>>>(bounds, slopes_prev, shifts_prev, bounds_prev, out, n_vec);
}